// round 6
// baseline (speedup 1.0000x reference)
#include <cuda_runtime.h>
#include <float.h>

#define CCH   512
#define HH    38
#define WW    63
#define HWN   (HH*WW)          /* 2394 */
#define NROI  1024
#define PRE   14               /* pre-pool grid 14x14 */
#define PS    7
#define TILE_STRIDE 513        /* 512 + 1 pad: conflict-free strided reads */
#define SMEM_BYTES  (49*TILE_STRIDE*4)   /* 100548 B */

// HWC-transposed feature map scratch (4.9 MB).
__device__ float g_hwc[HWN * CCH];

// ---------------------------------------------------------------------------
// Kernel 1: CHW -> HWC transpose (tiled, conflict-free)
// ---------------------------------------------------------------------------
__global__ void transpose_kernel(const float* __restrict__ src) {
    __shared__ float t[32][33];
    int hw0 = blockIdx.x * 32;
    int c0  = blockIdx.y * 32;

    int hw = hw0 + threadIdx.x;
#pragma unroll
    for (int dy = 0; dy < 32; dy += 8) {
        int c = c0 + threadIdx.y + dy;
        if (hw < HWN && c < CCH)
            t[threadIdx.y + dy][threadIdx.x] = src[c * HWN + hw];
    }
    __syncthreads();

    int c2 = c0 + threadIdx.x;
#pragma unroll
    for (int dy = 0; dy < 32; dy += 8) {
        int hh = hw0 + threadIdx.y + dy;
        if (hh < HWN && c2 < CCH)
            g_hwc[hh * CCH + c2] = t[threadIdx.x][threadIdx.y + dy];
    }
}

// ---------------------------------------------------------------------------
__device__ __forceinline__ float4 lerp4(float4 a, float4 b, float w) {
    float4 r;
    r.x = a.x + (b.x - a.x) * w;
    r.y = a.y + (b.y - a.y) * w;
    r.z = a.z + (b.z - a.z) * w;
    r.w = a.w + (b.w - a.w) * w;
    return r;
}
// running max with validity mask; applied immediately (short live ranges)
__device__ __forceinline__ void max4(float4& m, float4 v, bool valid) {
    float x = valid ? v.x : 0.f;
    float y = valid ? v.y : 0.f;
    float z = valid ? v.z : 0.f;
    float w = valid ? v.w : 0.f;
    m.x = fmaxf(m.x, x); m.y = fmaxf(m.y, y);
    m.z = fmaxf(m.z, z); m.w = fmaxf(m.w, w);
}

// ---------------------------------------------------------------------------
// Kernel 2: per-roi crop-and-resize (bilinear 14x14) + 2x2 maxpool -> 7x7.
// Each 128-lane group walks pooled COLUMNS (fixed px, py ascending) carrying a
// 2-row cache of horizontal-lerp results. y-samples are monotonic, so the
// cache gives exact cross-cell row dedup (~35% fewer global loads).
// ---------------------------------------------------------------------------
__global__ __launch_bounds__(512, 2)
void roi_kernel(const float* __restrict__ rois, float* __restrict__ out) {
    extern __shared__ float tile[];           // [49][TILE_STRIDE]

    // stage-1: per-sample
    __shared__ int   syo0[PRE], syo1[PRE];    // premultiplied row offsets (f4 units)
    __shared__ float swy[PRE];
    __shared__ unsigned svy[PRE];
    __shared__ int   sx0[PRE], sx1[PRE];
    __shared__ float swx[PRE];
    __shared__ unsigned svx[PRE];
    // stage-2: per pooled column (x only)
    __shared__ int   xC0[PS], xC1[PS], xC2[PS], xC3[PS], xCs[PS];
    __shared__ float xWa[PS], xWb[PS];
    __shared__ unsigned xVa[PS], xVb[PS];

    const int r   = blockIdx.x;
    const int tid = threadIdx.x;

    // --- stage 1: per-axis sample coords / weights / validity (ref math) ---
    if (tid < 2 * PRE) {
        bool isx = tid >= PRE;
        int  i   = isx ? tid - PRE : tid;
        float lo    = rois[5 * r + (isx ? 1 : 2)];
        float hi    = rois[5 * r + (isx ? 3 : 4)];
        float dimm1 = isx ? (float)(WW - 1) : (float)(HH - 1);
        float an = lo * 0.0625f / dimm1;
        float bn = hi * 0.0625f / dimm1;
        float t  = (float)i / 13.0f;
        float v  = (an + t * (bn - an)) * dimm1;
        float f  = floorf(v);
        int p0   = (int)f;
        int lim  = (int)dimm1;
        int q0   = min(max(p0, 0), lim);
        int q1   = min(max(p0 + 1, 0), lim);
        float w  = v - f;
        unsigned ok = (v >= 0.0f && v <= dimm1) ? 1u : 0u;
        if (isx) { sx0[i] = q0; sx1[i] = q1; swx[i] = w; svx[i] = ok; }
        else     { syo0[i] = q0 * (WW * 128); syo1[i] = q1 * (WW * 128);
                   swy[i] = w; svy[i] = ok; }
    }
    __syncthreads();

    // --- stage 2: per pooled column x structure + dedup case code ---
    if (tid < PS) {
        int q = tid;
        int i = 2 * q, j = 2 * q + 1;
        int C0 = sx0[i], C1 = sx1[i], C2 = sx0[j], C3 = sx1[j];
        xCs[q] = (C2 == C0) ? 0 : ((C2 == C1) ? 1 : 2);
        xC0[q] = C0 * 128; xC1[q] = C1 * 128;
        xC2[q] = C2 * 128; xC3[q] = C3 * 128;
        xWa[q] = swx[i]; xWb[q] = swx[j];
        xVa[q] = svx[i]; xVb[q] = svx[j];
    }
    __syncthreads();

    const int c4 = tid & 127;                           // float4 channel index
    const float4* __restrict__ base = (const float4*)g_hwc + c4;
    const int g = tid >> 7;                             // group 0..3

    // column-major cell ranges per group: 13,13,13,10
    int k    = (g < 3) ? 13 * g : 39;
    int kEnd = (g < 3) ? 13 * (g + 1) : 49;
    int px = k / 7;
    int py = k - px * 7;

    // x coefficients for current column
    int   c0 = xC0[px], c1 = xC1[px], c2 = xC2[px], c3 = xC3[px];
    int   xcs = xCs[px];
    float wxa = xWa[px], wxb = xWb[px];
    unsigned vxa = xVa[px], vxb = xVb[px];

    // horizontal interp for one row, deduping shared columns (uniform branch)
    auto hx_row = [&](int roff, float4& ha, float4& hb) {
        if (xcs == 0) {             // 2 unique cols
            float4 g0 = base[roff + c0];
            float4 g1 = base[roff + c1];
            ha = lerp4(g0, g1, wxa);
            hb = lerp4(g0, g1, wxb);
        } else if (xcs == 1) {      // 3 unique cols
            float4 g0 = base[roff + c0];
            float4 g1 = base[roff + c1];
            float4 g3 = base[roff + c3];
            ha = lerp4(g0, g1, wxa);
            hb = lerp4(g1, g3, wxb);
        } else {                    // 4 unique cols
            float4 g0 = base[roff + c0];
            float4 g1 = base[roff + c1];
            float4 g2 = base[roff + c2];
            float4 g3 = base[roff + c3];
            ha = lerp4(g0, g1, wxa);
            hb = lerp4(g2, g3, wxb);
        }
    };

    // 2-row cache of horizontal-lerp results (rows are monotonic in iy)
    int rLo = -1, rHi = -1;
    float4 hLoA, hLoB, hHiA, hHiB;

    while (k < kEnd) {
        float4 m = make_float4(-FLT_MAX, -FLT_MAX, -FLT_MAX, -FLT_MAX);

#pragma unroll
        for (int s = 0; s < 2; ++s) {
            const int iy = 2 * py + s;
            const int r0 = syo0[iy], r1 = syo1[iy];
            const float wy = swy[iy];
            const unsigned vy = svy[iy];

            float4 h0a, h0b, h1a, h1b;
            if (r0 == rLo)      { h0a = hLoA; h0b = hLoB; }
            else if (r0 == rHi) { h0a = hHiA; h0b = hHiB; }
            else                { hx_row(r0, h0a, h0b); }

            if (r1 == rHi)      { h1a = hHiA; h1b = hHiB; }
            else if (r1 == r0)  { h1a = h0a;  h1b = h0b;  }
            else                { hx_row(r1, h1a, h1b); }

            rLo = r0; hLoA = h0a; hLoB = h0b;
            rHi = r1; hHiA = h1a; hHiB = h1b;

            max4(m, lerp4(h0a, h1a, wy), (vy & vxa) != 0);
            max4(m, lerp4(h0b, h1b, wy), (vy & vxb) != 0);
        }

        // stage cell result: one STS.128, conflict-free
        int pos = py * 7 + px;
        float* row = tile + pos * TILE_STRIDE + c4 * 4;
        row[0] = m.x; row[1] = m.y; row[2] = m.z; row[3] = m.w;

        ++k; ++py;
        if (py == 7) {
            py = 0; ++px;
            if (k < kEnd) {
                c0 = xC0[px]; c1 = xC1[px]; c2 = xC2[px]; c3 = xC3[px];
                xcs = xCs[px];
                wxa = xWa[px]; wxb = xWb[px];
                vxa = xVa[px]; vxb = xVb[px];
                rLo = -1; rHi = -1;       // x-weights changed: invalidate cache
            }
        }
    }
    __syncthreads();

    // --- flush: out[r][c][pos] = tile[pos][c]; conflict-free + coalesced ---
    float* __restrict__ dst = out + (size_t)r * (CCH * 49);
    int c    = tid / 49;
    int pos2 = tid - c * 49;
    for (int j = tid; j < CCH * 49; j += 512) {
        dst[j] = tile[pos2 * TILE_STRIDE + c];
        pos2 += 22; c += 10;              // 512 = 10*49 + 22
        if (pos2 >= 49) { pos2 -= 49; ++c; }
    }
}

// ---------------------------------------------------------------------------
extern "C" void kernel_launch(void* const* d_in, const int* in_sizes, int n_in,
                              void* d_out, int out_size) {
    const float* bottom;
    const float* rois;
    if (n_in >= 2 && in_sizes[0] == 5 * NROI) {
        rois   = (const float*)d_in[0];
        bottom = (const float*)d_in[1];
    } else {
        bottom = (const float*)d_in[0];
        rois   = (const float*)d_in[1];
    }
    float* out = (float*)d_out;

    cudaFuncSetAttribute(roi_kernel,
                         cudaFuncAttributeMaxDynamicSharedMemorySize, SMEM_BYTES);

    dim3 tb(32, 8);
    dim3 tg((HWN + 31) / 32, (CCH + 31) / 32);
    transpose_kernel<<<tg, tb>>>(bottom);
    roi_kernel<<<NROI, 512, SMEM_BYTES>>>(rois, out);
}

// round 7
// speedup vs baseline: 1.1841x; 1.1841x over previous
#include <cuda_runtime.h>
#include <cuda_fp16.h>
#include <float.h>

#define CCH   512
#define HH    38
#define WW    63
#define HWN   (HH*WW)          /* 2394 */
#define NROI  1024
#define PRE   14               /* pre-pool grid 14x14 */
#define PS    7
#define TILE_STRIDE 513        /* 512 + 1 pad: conflict-free strided reads */
#define SMEM_BYTES  (49*TILE_STRIDE*4)   /* 100548 B */

// HWC-transposed fp16 feature map scratch (2.45 MB, L2-resident).
__device__ __half g_hwc_h[HWN * CCH];

// ---------------------------------------------------------------------------
// Kernel 1: CHW f32 -> HWC f16 transpose (tiled, conflict-free)
// ---------------------------------------------------------------------------
__global__ void transpose_kernel(const float* __restrict__ src) {
    __shared__ float t[32][33];
    int hw0 = blockIdx.x * 32;
    int c0  = blockIdx.y * 32;

    int hw = hw0 + threadIdx.x;
#pragma unroll
    for (int dy = 0; dy < 32; dy += 8) {
        int c = c0 + threadIdx.y + dy;
        if (hw < HWN && c < CCH)
            t[threadIdx.y + dy][threadIdx.x] = src[c * HWN + hw];
    }
    __syncthreads();

    int c2 = c0 + threadIdx.x;
#pragma unroll
    for (int dy = 0; dy < 32; dy += 8) {
        int hh = hw0 + threadIdx.y + dy;
        if (hh < HWN && c2 < CCH)
            g_hwc_h[hh * CCH + c2] = __float2half_rn(t[threadIdx.x][threadIdx.y + dy]);
    }
}

// ---------------------------------------------------------------------------
__device__ __forceinline__ float4 lerp4(float4 a, float4 b, float w) {
    float4 r;
    r.x = a.x + (b.x - a.x) * w;
    r.y = a.y + (b.y - a.y) * w;
    r.z = a.z + (b.z - a.z) * w;
    r.w = a.w + (b.w - a.w) * w;
    return r;
}
// running max with validity mask; applied immediately (short live ranges)
__device__ __forceinline__ void max4(float4& m, float4 v, bool valid) {
    float x = valid ? v.x : 0.f;
    float y = valid ? v.y : 0.f;
    float z = valid ? v.z : 0.f;
    float w = valid ? v.w : 0.f;
    m.x = fmaxf(m.x, x); m.y = fmaxf(m.y, y);
    m.z = fmaxf(m.z, z); m.w = fmaxf(m.w, w);
}

// ---------------------------------------------------------------------------
// Kernel 2: per-roi crop-and-resize (bilinear 14x14) + 2x2 maxpool -> 7x7,
// with uniform-branch dedup of shared corner rows/columns inside each cell.
// Feature fetches are fp16 (half the L1/L2 bytes), math in fp32.
// ---------------------------------------------------------------------------
__global__ __launch_bounds__(512, 2)
void roi_kernel(const float* __restrict__ rois, float* __restrict__ out) {
    extern __shared__ float tile[];           // [49][TILE_STRIDE]

    // stage-1: per-sample
    __shared__ int   sy0[PRE], sy1[PRE], sx0[PRE], sx1[PRE];
    __shared__ float swy[PRE], swx[PRE];
    __shared__ unsigned svy[PRE], svx[PRE];
    // stage-2: per pooled cell (premultiplied offsets in 4-channel units)
    __shared__ int   yR0[PS], yR1[PS], yR2[PS], yR3[PS], yCs[PS];
    __shared__ float yWa[PS], yWb[PS];
    __shared__ unsigned yVa[PS], yVb[PS];
    __shared__ int   xC0[PS], xC1[PS], xC2[PS], xC3[PS], xCs[PS];
    __shared__ float xWa[PS], xWb[PS];
    __shared__ unsigned xVa[PS], xVb[PS];

    const int r   = blockIdx.x;
    const int tid = threadIdx.x;

    // --- stage 1: per-axis sample coords / weights / validity (ref math) ---
    if (tid < 2 * PRE) {
        bool isx = tid >= PRE;
        int  i   = isx ? tid - PRE : tid;
        float lo    = rois[5 * r + (isx ? 1 : 2)];
        float hi    = rois[5 * r + (isx ? 3 : 4)];
        float dimm1 = isx ? (float)(WW - 1) : (float)(HH - 1);
        float an = lo * 0.0625f / dimm1;
        float bn = hi * 0.0625f / dimm1;
        float t  = (float)i / 13.0f;
        float v  = (an + t * (bn - an)) * dimm1;
        float f  = floorf(v);
        int p0   = (int)f;
        int lim  = (int)dimm1;
        int q0   = min(max(p0, 0), lim);
        int q1   = min(max(p0 + 1, 0), lim);
        float w  = v - f;
        unsigned ok = (v >= 0.0f && v <= dimm1) ? 1u : 0u;
        if (isx) { sx0[i] = q0; sx1[i] = q1; swx[i] = w; svx[i] = ok; }
        else     { sy0[i] = q0; sy1[i] = q1; swy[i] = w; svy[i] = ok; }
    }
    __syncthreads();

    // --- stage 2: per pooled cell structure + dedup case codes ---
    if (tid < 2 * PS) {
        bool isx = tid >= PS;
        int  q   = isx ? tid - PS : tid;
        int  i = 2 * q, j = 2 * q + 1;
        if (!isx) {
            int R0 = sy0[i], R1 = sy1[i], R2 = sy0[j], R3 = sy1[j];
            yCs[q] = (R2 == R0) ? 0 : ((R2 == R1) ? 1 : 2);
            yR0[q] = R0 * (WW * 128); yR1[q] = R1 * (WW * 128);
            yR2[q] = R2 * (WW * 128); yR3[q] = R3 * (WW * 128);
            yWa[q] = swy[i]; yWb[q] = swy[j];
            yVa[q] = svy[i]; yVb[q] = svy[j];
        } else {
            int C0 = sx0[i], C1 = sx1[i], C2 = sx0[j], C3 = sx1[j];
            xCs[q] = (C2 == C0) ? 0 : ((C2 == C1) ? 1 : 2);
            xC0[q] = C0 * 128; xC1[q] = C1 * 128;
            xC2[q] = C2 * 128; xC3[q] = C3 * 128;
            xWa[q] = swx[i]; xWb[q] = swx[j];
            xVa[q] = svx[i]; xVb[q] = svx[j];
        }
    }
    __syncthreads();

    const int c4 = tid & 127;                     // 4-channel lane index
    // base in uint2 units: one uint2 == 4 halves == 4 channels
    const uint2* __restrict__ base = (const uint2*)g_hwc_h + c4;

    // fp16 corner fetch -> fp32 lane values
    auto ldc = [&](int off) -> float4 {
        uint2 g = base[off];
        float2 f0 = __half22float2(*reinterpret_cast<__half2*>(&g.x));
        float2 f1 = __half22float2(*reinterpret_cast<__half2*>(&g.y));
        return make_float4(f0.x, f0.y, f1.x, f1.y);
    };

    int pos = tid >> 7;      // 0..3
    int py  = 0;
    int px  = pos;
    while (pos < 49) {
        const int   c0 = xC0[px], c1 = xC1[px], c2 = xC2[px], c3 = xC3[px];
        const int   xcs = xCs[px];
        const float wxa = xWa[px], wxb = xWb[px];
        const int   r0 = yR0[py], r1 = yR1[py], r2 = yR2[py], r3 = yR3[py];
        const int   ycs = yCs[py];
        const float wya = yWa[py], wyb = yWb[py];
        const bool  vaa = (yVa[py] & xVa[px]) != 0;
        const bool  vab = (yVa[py] & xVb[px]) != 0;
        const bool  vba = (yVb[py] & xVa[px]) != 0;
        const bool  vbb = (yVb[py] & xVb[px]) != 0;

        // horizontal interp for one row, deduping shared columns (uniform branch)
        auto hx_row = [&](int roff, float4& ha, float4& hb) {
            if (xcs == 0) {             // 2 unique cols
                float4 g0 = ldc(roff + c0);
                float4 g1 = ldc(roff + c1);
                ha = lerp4(g0, g1, wxa);
                hb = lerp4(g0, g1, wxb);
            } else if (xcs == 1) {      // 3 unique cols
                float4 g0 = ldc(roff + c0);
                float4 g1 = ldc(roff + c1);
                float4 g3 = ldc(roff + c3);
                ha = lerp4(g0, g1, wxa);
                hb = lerp4(g1, g3, wxb);
            } else {                    // 4 unique cols
                float4 g0 = ldc(roff + c0);
                float4 g1 = ldc(roff + c1);
                float4 g2 = ldc(roff + c2);
                float4 g3 = ldc(roff + c3);
                ha = lerp4(g0, g1, wxa);
                hb = lerp4(g2, g3, wxb);
            }
        };

        float4 m = make_float4(-FLT_MAX, -FLT_MAX, -FLT_MAX, -FLT_MAX);

        float4 h0a, h0b, h1a, h1b;
        hx_row(r0, h0a, h0b);
        hx_row(r1, h1a, h1b);
        max4(m, lerp4(h0a, h1a, wya), vaa);
        max4(m, lerp4(h0b, h1b, wya), vab);

        float4 h2a, h2b, h3a, h3b;
        if (ycs == 0) {                 // reuse both rows
            h2a = h0a; h2b = h0b; h3a = h1a; h3b = h1b;
        } else if (ycs == 1) {          // reuse one row
            h2a = h1a; h2b = h1b;
            hx_row(r3, h3a, h3b);
        } else {
            hx_row(r2, h2a, h2b);
            hx_row(r3, h3a, h3b);
        }
        max4(m, lerp4(h2a, h3a, wyb), vba);
        max4(m, lerp4(h2b, h3b, wyb), vbb);

        // stage into shared: 4 consecutive words -> one STS.128, conflict-free
        float* row = tile + pos * TILE_STRIDE + c4 * 4;
        row[0] = m.x; row[1] = m.y; row[2] = m.z; row[3] = m.w;

        pos += 4;
        px  += 4;
        if (px >= 7) { px -= 7; ++py; }
    }
    __syncthreads();

    // --- flush: out[r][c][pos] = tile[pos][c]; conflict-free + coalesced ---
    float* __restrict__ dst = out + (size_t)r * (CCH * 49);
    int c    = tid / 49;
    int pos2 = tid - c * 49;
    for (int j = tid; j < CCH * 49; j += 512) {
        dst[j] = tile[pos2 * TILE_STRIDE + c];
        pos2 += 22; c += 10;              // 512 = 10*49 + 22
        if (pos2 >= 49) { pos2 -= 49; ++c; }
    }
}

// ---------------------------------------------------------------------------
extern "C" void kernel_launch(void* const* d_in, const int* in_sizes, int n_in,
                              void* d_out, int out_size) {
    const float* bottom;
    const float* rois;
    if (n_in >= 2 && in_sizes[0] == 5 * NROI) {
        rois   = (const float*)d_in[0];
        bottom = (const float*)d_in[1];
    } else {
        bottom = (const float*)d_in[0];
        rois   = (const float*)d_in[1];
    }
    float* out = (float*)d_out;

    cudaFuncSetAttribute(roi_kernel,
                         cudaFuncAttributeMaxDynamicSharedMemorySize, SMEM_BYTES);

    dim3 tb(32, 8);
    dim3 tg((HWN + 31) / 32, (CCH + 31) / 32);
    transpose_kernel<<<tg, tb>>>(bottom);
    roi_kernel<<<NROI, 512, SMEM_BYTES>>>(rois, out);
}

// round 8
// speedup vs baseline: 1.3963x; 1.1793x over previous
#include <cuda_runtime.h>
#include <cuda_fp16.h>
#include <float.h>

#define CCH   512
#define HH    38
#define WW    63
#define HWN   (HH*WW)          /* 2394 */
#define NROI  1024
#define PRE   14               /* pre-pool grid 14x14 */
#define PS    7
#define TILE_STRIDE 513        /* 512 + 1 pad: conflict-free strided reads */
#define SMEM_BYTES  (49*TILE_STRIDE*4)   /* 100548 B */

// HWC-transposed fp16 feature map scratch (2.45 MB, L2-resident).
__device__ __half g_hwc_h[HWN * CCH];

// ---------------------------------------------------------------------------
// Kernel 1: CHW f32 -> HWC f16 transpose (tiled, conflict-free)
// ---------------------------------------------------------------------------
__global__ void transpose_kernel(const float* __restrict__ src) {
    __shared__ float t[32][33];
    int hw0 = blockIdx.x * 32;
    int c0  = blockIdx.y * 32;

    int hw = hw0 + threadIdx.x;
#pragma unroll
    for (int dy = 0; dy < 32; dy += 8) {
        int c = c0 + threadIdx.y + dy;
        if (hw < HWN && c < CCH)
            t[threadIdx.y + dy][threadIdx.x] = src[c * HWN + hw];
    }
    __syncthreads();

    int c2 = c0 + threadIdx.x;
#pragma unroll
    for (int dy = 0; dy < 32; dy += 8) {
        int hh = hw0 + threadIdx.y + dy;
        if (hh < HWN && c2 < CCH)
            g_hwc_h[hh * CCH + c2] = __float2half_rn(t[threadIdx.x][threadIdx.y + dy]);
    }
}

// ---------------------------------------------------------------------------
// 4 channels as 2x half2
struct H4 { __half2 lo, hi; };

__device__ __forceinline__ H4 lerpH(H4 a, H4 b, __half2 w) {
    H4 r;
    r.lo = __hfma2(__hsub2(b.lo, a.lo), w, a.lo);
    r.hi = __hfma2(__hsub2(b.hi, a.hi), w, a.hi);
    return r;
}
// mask (bitwise AND with 0x0/0xFFFFFFFF) then running max; exact in fp16
__device__ __forceinline__ void maxH(H4& m, H4 v, unsigned mb) {
    unsigned lo = (reinterpret_cast<unsigned&>(v.lo)) & mb;
    unsigned hi = (reinterpret_cast<unsigned&>(v.hi)) & mb;
    m.lo = __hmax2(m.lo, reinterpret_cast<__half2&>(lo));
    m.hi = __hmax2(m.hi, reinterpret_cast<__half2&>(hi));
}

// ---------------------------------------------------------------------------
// Kernel 2: per-roi crop-and-resize (bilinear 14x14) + 2x2 maxpool -> 7x7.
// All interpolation in packed half2 (HSUB2/HFMA2/HMAX2); only the final 4
// pooled values per cell are converted to f32 for staging.
// ---------------------------------------------------------------------------
__global__ __launch_bounds__(512, 2)
void roi_kernel(const float* __restrict__ rois, float* __restrict__ out) {
    extern __shared__ float tile[];           // [49][TILE_STRIDE]

    // stage-1: per-sample
    __shared__ int     sy0[PRE], sy1[PRE], sx0[PRE], sx1[PRE];
    __shared__ float   swx_f[PRE];
    __shared__ __half2 swy[PRE];
    __shared__ unsigned svy[PRE], svx[PRE];
    // stage-2: per pooled cell (premultiplied offsets in 4-channel units)
    __shared__ int     yR0[PS], yR1[PS], yR2[PS], yR3[PS], yCs[PS];
    __shared__ unsigned yVa[PS], yVb[PS];
    __shared__ int     xC0[PS], xC1[PS], xC2[PS], xC3[PS], xCs[PS];
    __shared__ __half2 xWa[PS], xWb[PS];
    __shared__ unsigned xVa[PS], xVb[PS];

    const int r   = blockIdx.x;
    const int tid = threadIdx.x;

    // --- stage 1: per-axis sample coords / weights / validity (ref math) ---
    if (tid < 2 * PRE) {
        bool isx = tid >= PRE;
        int  i   = isx ? tid - PRE : tid;
        float lo    = rois[5 * r + (isx ? 1 : 2)];
        float hi    = rois[5 * r + (isx ? 3 : 4)];
        float dimm1 = isx ? (float)(WW - 1) : (float)(HH - 1);
        float an = lo * 0.0625f / dimm1;
        float bn = hi * 0.0625f / dimm1;
        float t  = (float)i / 13.0f;
        float v  = (an + t * (bn - an)) * dimm1;
        float f  = floorf(v);
        int p0   = (int)f;
        int lim  = (int)dimm1;
        int q0   = min(max(p0, 0), lim);
        int q1   = min(max(p0 + 1, 0), lim);
        float w  = v - f;
        unsigned ok = (v >= 0.0f && v <= dimm1) ? 1u : 0u;
        if (isx) { sx0[i] = q0; sx1[i] = q1; swx_f[i] = w; svx[i] = ok; }
        else     { sy0[i] = q0; sy1[i] = q1;
                   swy[i] = __float2half2_rn(w); svy[i] = ok; }
    }
    __syncthreads();

    // --- stage 2: per pooled cell structure + dedup case codes ---
    if (tid < 2 * PS) {
        bool isx = tid >= PS;
        int  q   = isx ? tid - PS : tid;
        int  i = 2 * q, j = 2 * q + 1;
        if (!isx) {
            int R0 = sy0[i], R1 = sy1[i], R2 = sy0[j], R3 = sy1[j];
            yCs[q] = (R2 == R0) ? 0 : ((R2 == R1) ? 1 : 2);
            yR0[q] = R0 * (WW * 128); yR1[q] = R1 * (WW * 128);
            yR2[q] = R2 * (WW * 128); yR3[q] = R3 * (WW * 128);
            yVa[q] = svy[i]; yVb[q] = svy[j];
        } else {
            int C0 = sx0[i], C1 = sx1[i], C2 = sx0[j], C3 = sx1[j];
            xCs[q] = (C2 == C0) ? 0 : ((C2 == C1) ? 1 : 2);
            xC0[q] = C0 * 128; xC1[q] = C1 * 128;
            xC2[q] = C2 * 128; xC3[q] = C3 * 128;
            xWa[q] = __float2half2_rn(swx_f[i]);
            xWb[q] = __float2half2_rn(swx_f[j]);
            xVa[q] = svx[i]; xVb[q] = svx[j];
        }
    }
    __syncthreads();

    const int c4 = tid & 127;                     // 4-channel lane index
    const uint2* __restrict__ base = (const uint2*)g_hwc_h + c4;

    auto ldc = [&](int off) -> H4 {
        uint2 g = base[off];
        H4 h;
        h.lo = reinterpret_cast<__half2&>(g.x);
        h.hi = reinterpret_cast<__half2&>(g.y);
        return h;
    };

    const unsigned NEGINF2 = 0xFC00FC00u;         // half2(-inf,-inf)

    int pos = tid >> 7;      // 0..3
    int py  = 0;
    int px  = pos;
    while (pos < 49) {
        const int     c0 = xC0[px], c1 = xC1[px], c2 = xC2[px], c3 = xC3[px];
        const int     xcs = xCs[px];
        const __half2 wxa = xWa[px], wxb = xWb[px];
        const int     r0 = yR0[py], r1 = yR1[py], r2 = yR2[py], r3 = yR3[py];
        const int     ycs = yCs[py];
        const __half2 wya = swy[2 * py], wyb = swy[2 * py + 1];
        // full-word masks: 0xFFFFFFFF if valid else 0
        const unsigned maa = (unsigned)-(int)(yVa[py] & xVa[px]);
        const unsigned mab = (unsigned)-(int)(yVa[py] & xVb[px]);
        const unsigned mba = (unsigned)-(int)(yVb[py] & xVa[px]);
        const unsigned mbb = (unsigned)-(int)(yVb[py] & xVb[px]);

        // horizontal interp for one row, deduping shared columns (uniform branch)
        auto hx_row = [&](int roff, H4& ha, H4& hb) {
            if (xcs == 0) {             // 2 unique cols
                H4 g0 = ldc(roff + c0);
                H4 g1 = ldc(roff + c1);
                ha = lerpH(g0, g1, wxa);
                hb = lerpH(g0, g1, wxb);
            } else if (xcs == 1) {      // 3 unique cols
                H4 g0 = ldc(roff + c0);
                H4 g1 = ldc(roff + c1);
                H4 g3 = ldc(roff + c3);
                ha = lerpH(g0, g1, wxa);
                hb = lerpH(g1, g3, wxb);
            } else {                    // 4 unique cols
                H4 g0 = ldc(roff + c0);
                H4 g1 = ldc(roff + c1);
                H4 g2 = ldc(roff + c2);
                H4 g3 = ldc(roff + c3);
                ha = lerpH(g0, g1, wxa);
                hb = lerpH(g2, g3, wxb);
            }
        };

        H4 m;
        m.lo = reinterpret_cast<const __half2&>(NEGINF2);
        m.hi = reinterpret_cast<const __half2&>(NEGINF2);

        H4 h0a, h0b, h1a, h1b;
        hx_row(r0, h0a, h0b);
        hx_row(r1, h1a, h1b);
        maxH(m, lerpH(h0a, h1a, wya), maa);
        maxH(m, lerpH(h0b, h1b, wya), mab);

        H4 h2a, h2b, h3a, h3b;
        if (ycs == 0) {                 // reuse both rows
            h2a = h0a; h2b = h0b; h3a = h1a; h3b = h1b;
        } else if (ycs == 1) {          // reuse one row
            h2a = h1a; h2b = h1b;
            hx_row(r3, h3a, h3b);
        } else {
            hx_row(r2, h2a, h2b);
            hx_row(r3, h3a, h3b);
        }
        maxH(m, lerpH(h2a, h3a, wyb), mba);
        maxH(m, lerpH(h2b, h3b, wyb), mbb);

        // convert pooled result to f32, stage: one STS.128, conflict-free
        float2 f0 = __half22float2(m.lo);
        float2 f1 = __half22float2(m.hi);
        float* row = tile + pos * TILE_STRIDE + c4 * 4;
        row[0] = f0.x; row[1] = f0.y; row[2] = f1.x; row[3] = f1.y;

        pos += 4;
        px  += 4;
        if (px >= 7) { px -= 7; ++py; }
    }
    __syncthreads();

    // --- flush: out[r][c][pos] = tile[pos][c]; conflict-free + coalesced ---
    float* __restrict__ dst = out + (size_t)r * (CCH * 49);
    int c    = tid / 49;
    int pos2 = tid - c * 49;
    for (int j = tid; j < CCH * 49; j += 512) {
        dst[j] = tile[pos2 * TILE_STRIDE + c];
        pos2 += 22; c += 10;              // 512 = 10*49 + 22
        if (pos2 >= 49) { pos2 -= 49; ++c; }
    }
}

// ---------------------------------------------------------------------------
extern "C" void kernel_launch(void* const* d_in, const int* in_sizes, int n_in,
                              void* d_out, int out_size) {
    const float* bottom;
    const float* rois;
    if (n_in >= 2 && in_sizes[0] == 5 * NROI) {
        rois   = (const float*)d_in[0];
        bottom = (const float*)d_in[1];
    } else {
        bottom = (const float*)d_in[0];
        rois   = (const float*)d_in[1];
    }
    float* out = (float*)d_out;

    cudaFuncSetAttribute(roi_kernel,
                         cudaFuncAttributeMaxDynamicSharedMemorySize, SMEM_BYTES);

    dim3 tb(32, 8);
    dim3 tg((HWN + 31) / 32, (CCH + 31) / 32);
    transpose_kernel<<<tg, tb>>>(bottom);
    roi_kernel<<<NROI, 512, SMEM_BYTES>>>(rois, out);
}

// round 9
// speedup vs baseline: 1.5949x; 1.1422x over previous
#include <cuda_runtime.h>
#include <cuda_fp16.h>
#include <float.h>

#define CCH   512
#define HH    38
#define WW    63
#define HWN   (HH*WW)          /* 2394 */
#define NROI  1024
#define PRE   14               /* pre-pool grid 14x14 */
#define PS    7
#define TILE_STRIDE 513        /* bank-stride-1 on flush reads */
#define SMEM_BYTES  (49*TILE_STRIDE*4)   /* 100548 B */

// HWC-transposed fp16 feature map scratch (2.45 MB, L2-resident).
__device__ __half g_hwc_h[HWN * CCH];

// ---------------------------------------------------------------------------
// Kernel 1: CHW f32 -> HWC f16 transpose (tiled, conflict-free)
// ---------------------------------------------------------------------------
__global__ void transpose_kernel(const float* __restrict__ src) {
    __shared__ float t[32][33];
    int hw0 = blockIdx.x * 32;
    int c0  = blockIdx.y * 32;

    int hw = hw0 + threadIdx.x;
#pragma unroll
    for (int dy = 0; dy < 32; dy += 8) {
        int c = c0 + threadIdx.y + dy;
        if (hw < HWN && c < CCH)
            t[threadIdx.y + dy][threadIdx.x] = src[c * HWN + hw];
    }
    __syncthreads();

    int c2 = c0 + threadIdx.x;
#pragma unroll
    for (int dy = 0; dy < 32; dy += 8) {
        int hh = hw0 + threadIdx.y + dy;
        if (hh < HWN && c2 < CCH)
            g_hwc_h[hh * CCH + c2] = __float2half_rn(t[threadIdx.x][threadIdx.y + dy]);
    }
}

// ---------------------------------------------------------------------------
// 8 channels as 4x half2
struct H8 { __half2 a, b, c, d; };

__device__ __forceinline__ H8 lerpH(H8 p, H8 q, __half2 w) {
    H8 r;
    r.a = __hfma2(__hsub2(q.a, p.a), w, p.a);
    r.b = __hfma2(__hsub2(q.b, p.b), w, p.b);
    r.c = __hfma2(__hsub2(q.c, p.c), w, p.c);
    r.d = __hfma2(__hsub2(q.d, p.d), w, p.d);
    return r;
}
// mask (AND with 0/0xFFFFFFFF) then running max; exact in fp16
__device__ __forceinline__ void maxH(H8& m, H8 v, unsigned mb) {
    unsigned a = reinterpret_cast<unsigned&>(v.a) & mb;
    unsigned b = reinterpret_cast<unsigned&>(v.b) & mb;
    unsigned c = reinterpret_cast<unsigned&>(v.c) & mb;
    unsigned d = reinterpret_cast<unsigned&>(v.d) & mb;
    m.a = __hmax2(m.a, reinterpret_cast<__half2&>(a));
    m.b = __hmax2(m.b, reinterpret_cast<__half2&>(b));
    m.c = __hmax2(m.c, reinterpret_cast<__half2&>(c));
    m.d = __hmax2(m.d, reinterpret_cast<__half2&>(d));
}

// ---------------------------------------------------------------------------
// Kernel 2: per-roi crop-and-resize (bilinear 14x14) + 2x2 maxpool -> 7x7.
// 8 groups x 64 lanes; each lane owns 8 consecutive channels (one LDG.128 per
// corner per lane). Math in packed half2. Staging column permutation
// col = c8 + 64*m keeps scalar STS lane-stride 1 (conflict-free).
// ---------------------------------------------------------------------------
__global__ __launch_bounds__(512, 2)
void roi_kernel(const float* __restrict__ rois, float* __restrict__ out) {
    extern __shared__ float tile[];           // [49][TILE_STRIDE]

    // stage-1: per-sample
    __shared__ int     sy0[PRE], sy1[PRE], sx0[PRE], sx1[PRE];
    __shared__ float   swx_f[PRE];
    __shared__ __half2 swy[PRE];
    __shared__ unsigned svy[PRE], svx[PRE];
    // stage-2: per pooled cell (premultiplied offsets in uint4/8-channel units)
    __shared__ int     yR0[PS], yR1[PS], yR2[PS], yR3[PS], yCs[PS];
    __shared__ unsigned yVa[PS], yVb[PS];
    __shared__ int     xC0[PS], xC1[PS], xC2[PS], xC3[PS], xCs[PS];
    __shared__ __half2 xWa[PS], xWb[PS];
    __shared__ unsigned xVa[PS], xVb[PS];

    const int r   = blockIdx.x;
    const int tid = threadIdx.x;

    // --- stage 1: per-axis sample coords / weights / validity (ref math) ---
    if (tid < 2 * PRE) {
        bool isx = tid >= PRE;
        int  i   = isx ? tid - PRE : tid;
        float lo    = rois[5 * r + (isx ? 1 : 2)];
        float hi    = rois[5 * r + (isx ? 3 : 4)];
        float dimm1 = isx ? (float)(WW - 1) : (float)(HH - 1);
        float an = lo * 0.0625f / dimm1;
        float bn = hi * 0.0625f / dimm1;
        float t  = (float)i / 13.0f;
        float v  = (an + t * (bn - an)) * dimm1;
        float f  = floorf(v);
        int p0   = (int)f;
        int lim  = (int)dimm1;
        int q0   = min(max(p0, 0), lim);
        int q1   = min(max(p0 + 1, 0), lim);
        float w  = v - f;
        unsigned ok = (v >= 0.0f && v <= dimm1) ? 1u : 0u;
        if (isx) { sx0[i] = q0; sx1[i] = q1; swx_f[i] = w; svx[i] = ok; }
        else     { sy0[i] = q0; sy1[i] = q1;
                   swy[i] = __float2half2_rn(w); svy[i] = ok; }
    }
    __syncthreads();

    // --- stage 2: per pooled cell structure + dedup case codes ---
    if (tid < 2 * PS) {
        bool isx = tid >= PS;
        int  q   = isx ? tid - PS : tid;
        int  i = 2 * q, j = 2 * q + 1;
        if (!isx) {
            int R0 = sy0[i], R1 = sy1[i], R2 = sy0[j], R3 = sy1[j];
            yCs[q] = (R2 == R0) ? 0 : ((R2 == R1) ? 1 : 2);
            yR0[q] = R0 * (WW * 64); yR1[q] = R1 * (WW * 64);
            yR2[q] = R2 * (WW * 64); yR3[q] = R3 * (WW * 64);
            yVa[q] = svy[i]; yVb[q] = svy[j];
        } else {
            int C0 = sx0[i], C1 = sx1[i], C2 = sx0[j], C3 = sx1[j];
            xCs[q] = (C2 == C0) ? 0 : ((C2 == C1) ? 1 : 2);
            xC0[q] = C0 * 64; xC1[q] = C1 * 64;
            xC2[q] = C2 * 64; xC3[q] = C3 * 64;
            xWa[q] = __float2half2_rn(swx_f[i]);
            xWb[q] = __float2half2_rn(swx_f[j]);
            xVa[q] = svx[i]; xVb[q] = svx[j];
        }
    }
    __syncthreads();

    const int c8 = tid & 63;                      // 8-channel lane index
    const uint4* __restrict__ base = (const uint4*)g_hwc_h + c8;

    auto ldc = [&](int off) -> H8 {
        uint4 g = base[off];
        H8 h;
        h.a = reinterpret_cast<__half2&>(g.x);
        h.b = reinterpret_cast<__half2&>(g.y);
        h.c = reinterpret_cast<__half2&>(g.z);
        h.d = reinterpret_cast<__half2&>(g.w);
        return h;
    };

    const unsigned NEGINF2 = 0xFC00FC00u;         // half2(-inf,-inf)

    int pos = tid >> 6;      // group 0..7
    int py  = pos / 7;       // 0 (or 1 for g=7)
    int px  = pos - py * 7;
    while (pos < 49) {
        const int     c0 = xC0[px], c1 = xC1[px], c2 = xC2[px], c3 = xC3[px];
        const int     xcs = xCs[px];
        const __half2 wxa = xWa[px], wxb = xWb[px];
        const int     r0 = yR0[py], r1 = yR1[py], r2 = yR2[py], r3 = yR3[py];
        const int     ycs = yCs[py];
        const __half2 wya = swy[2 * py], wyb = swy[2 * py + 1];
        const unsigned maa = (unsigned)-(int)(yVa[py] & xVa[px]);
        const unsigned mab = (unsigned)-(int)(yVa[py] & xVb[px]);
        const unsigned mba = (unsigned)-(int)(yVb[py] & xVa[px]);
        const unsigned mbb = (unsigned)-(int)(yVb[py] & xVb[px]);

        // horizontal interp for one row, deduping shared columns (uniform branch)
        auto hx_row = [&](int roff, H8& ha, H8& hb) {
            if (xcs == 0) {             // 2 unique cols
                H8 g0 = ldc(roff + c0);
                H8 g1 = ldc(roff + c1);
                ha = lerpH(g0, g1, wxa);
                hb = lerpH(g0, g1, wxb);
            } else if (xcs == 1) {      // 3 unique cols
                H8 g0 = ldc(roff + c0);
                H8 g1 = ldc(roff + c1);
                H8 g3 = ldc(roff + c3);
                ha = lerpH(g0, g1, wxa);
                hb = lerpH(g1, g3, wxb);
            } else {                    // 4 unique cols
                H8 g0 = ldc(roff + c0);
                H8 g1 = ldc(roff + c1);
                H8 g2 = ldc(roff + c2);
                H8 g3 = ldc(roff + c3);
                ha = lerpH(g0, g1, wxa);
                hb = lerpH(g2, g3, wxb);
            }
        };

        H8 m;
        m.a = reinterpret_cast<const __half2&>(NEGINF2);
        m.b = m.a; m.c = m.a; m.d = m.a;

        H8 h0a, h0b, h1a, h1b;
        hx_row(r0, h0a, h0b);
        hx_row(r1, h1a, h1b);
        maxH(m, lerpH(h0a, h1a, wya), maa);
        maxH(m, lerpH(h0b, h1b, wya), mab);

        H8 h2a, h2b, h3a, h3b;
        if (ycs == 0) {                 // reuse both rows
            h2a = h0a; h2b = h0b; h3a = h1a; h3b = h1b;
        } else if (ycs == 1) {          // reuse one row
            h2a = h1a; h2b = h1b;
            hx_row(r3, h3a, h3b);
        } else {
            hx_row(r2, h2a, h2b);
            hx_row(r3, h3a, h3b);
        }
        maxH(m, lerpH(h2a, h3a, wyb), mba);
        maxH(m, lerpH(h2b, h3b, wyb), mbb);

        // stage: channel c8*8+m -> column c8 + 64*m (lane-stride 1, no conflicts)
        float* st = tile + pos * TILE_STRIDE + c8;
        float2 f;
        f = __half22float2(m.a); st[0]       = f.x; st[64]      = f.y;
        f = __half22float2(m.b); st[128]     = f.x; st[192]     = f.y;
        f = __half22float2(m.c); st[256]     = f.x; st[320]     = f.y;
        f = __half22float2(m.d); st[384]     = f.x; st[448]     = f.y;

        pos += 8;
        px  += 1;
        py  += 1;
        if (px >= 7) { px -= 7; ++py; }
    }
    __syncthreads();

    // --- flush: out[r][c][pos] = tile[pos][col(c)], col = (c>>3)+((c&7)<<6)
    //     reads bank-stride-1 (conflict-free), stores fully coalesced ---
    float* __restrict__ dst = out + (size_t)r * (CCH * 49);
    int c    = tid / 49;
    int pos2 = tid - c * 49;
    for (int j = tid; j < CCH * 49; j += 512) {
        int col = (c >> 3) + ((c & 7) << 6);
        dst[j] = tile[pos2 * TILE_STRIDE + col];
        pos2 += 22; c += 10;              // 512 = 10*49 + 22
        if (pos2 >= 49) { pos2 -= 49; ++c; }
    }
}

// ---------------------------------------------------------------------------
extern "C" void kernel_launch(void* const* d_in, const int* in_sizes, int n_in,
                              void* d_out, int out_size) {
    const float* bottom;
    const float* rois;
    if (n_in >= 2 && in_sizes[0] == 5 * NROI) {
        rois   = (const float*)d_in[0];
        bottom = (const float*)d_in[1];
    } else {
        bottom = (const float*)d_in[0];
        rois   = (const float*)d_in[1];
    }
    float* out = (float*)d_out;

    cudaFuncSetAttribute(roi_kernel,
                         cudaFuncAttributeMaxDynamicSharedMemorySize, SMEM_BYTES);

    dim3 tb(32, 8);
    dim3 tg((HWN + 31) / 32, (CCH + 31) / 32);
    transpose_kernel<<<tg, tb>>>(bottom);
    roi_kernel<<<NROI, 512, SMEM_BYTES>>>(rois, out);
}

// round 10
// speedup vs baseline: 1.6525x; 1.0361x over previous
#include <cuda_runtime.h>
#include <cuda_fp16.h>
#include <float.h>

#define CCH   512
#define HH    38
#define WW    63
#define HWN   (HH*WW)          /* 2394 */
#define NROI  1024
#define PRE   14               /* pre-pool grid 14x14 */
#define PS    7
#define TSTRIDE 257            /* 256 half2-words + 1 pad: conflict-free flush */
#define SMEM_BYTES (49*TSTRIDE*4)  /* 50372 B */

// HWC-transposed fp16 feature map scratch (2.45 MB, L2-resident).
__device__ __half g_hwc_h[HWN * CCH];

// ---------------------------------------------------------------------------
// Kernel 1: CHW f32 -> HWC f16 transpose (tiled, conflict-free)
// ---------------------------------------------------------------------------
__global__ void transpose_kernel(const float* __restrict__ src) {
    __shared__ float t[32][33];
    int hw0 = blockIdx.x * 32;
    int c0  = blockIdx.y * 32;

    int hw = hw0 + threadIdx.x;
#pragma unroll
    for (int dy = 0; dy < 32; dy += 8) {
        int c = c0 + threadIdx.y + dy;
        if (hw < HWN && c < CCH)
            t[threadIdx.y + dy][threadIdx.x] = src[c * HWN + hw];
    }
    __syncthreads();

    int c2 = c0 + threadIdx.x;
#pragma unroll
    for (int dy = 0; dy < 32; dy += 8) {
        int hh = hw0 + threadIdx.y + dy;
        if (hh < HWN && c2 < CCH)
            g_hwc_h[hh * CCH + c2] = __float2half_rn(t[threadIdx.x][threadIdx.y + dy]);
    }
}

// ---------------------------------------------------------------------------
// 8 channels as 4x half2
struct H8 { __half2 a, b, c, d; };

__device__ __forceinline__ H8 lerpH(H8 p, H8 q, __half2 w) {
    H8 r;
    r.a = __hfma2(__hsub2(q.a, p.a), w, p.a);
    r.b = __hfma2(__hsub2(q.b, p.b), w, p.b);
    r.c = __hfma2(__hsub2(q.c, p.c), w, p.c);
    r.d = __hfma2(__hsub2(q.d, p.d), w, p.d);
    return r;
}
// running max with half2 0/1 mask applied via HMUL2 (fma pipe, not alu)
__device__ __forceinline__ void maxH(H8& m, H8 v, __half2 mk) {
    m.a = __hmax2(m.a, __hmul2(v.a, mk));
    m.b = __hmax2(m.b, __hmul2(v.b, mk));
    m.c = __hmax2(m.c, __hmul2(v.c, mk));
    m.d = __hmax2(m.d, __hmul2(v.d, mk));
}

// ---------------------------------------------------------------------------
// Kernel 2: per-roi crop-and-resize (bilinear 14x14) + 2x2 maxpool -> 7x7.
// 8 groups x 64 lanes; each lane owns 8 consecutive channels (one LDG.128 per
// corner). Math in packed half2. Results staged as half2 words, converted to
// f32 only during the coalesced flush.
// ---------------------------------------------------------------------------
__global__ __launch_bounds__(512, 2)
void roi_kernel(const float* __restrict__ rois, float* __restrict__ out) {
    extern __shared__ unsigned tile_u[];      // [49][TSTRIDE] half2 words

    // stage-1: per-sample
    __shared__ int     sy0[PRE], sy1[PRE], sx0[PRE], sx1[PRE];
    __shared__ float   swx_f[PRE];
    __shared__ __half2 swy[PRE];
    __shared__ unsigned svy[PRE], svx[PRE];   // 0x3C003C00 (1.0h2) or 0
    // stage-2: per pooled cell (premultiplied offsets in uint4/8-channel units)
    __shared__ int     yR0[PS], yR1[PS], yR2[PS], yR3[PS], yCs[PS];
    __shared__ unsigned yVa[PS], yVb[PS];
    __shared__ int     xC0[PS], xC1[PS], xC2[PS], xC3[PS], xCs[PS];
    __shared__ __half2 xWa[PS], xWb[PS];
    __shared__ unsigned xVa[PS], xVb[PS];

    const int r   = blockIdx.x;
    const int tid = threadIdx.x;

    // --- stage 1: per-axis sample coords / weights / validity (ref math) ---
    if (tid < 2 * PRE) {
        bool isx = tid >= PRE;
        int  i   = isx ? tid - PRE : tid;
        float lo    = rois[5 * r + (isx ? 1 : 2)];
        float hi    = rois[5 * r + (isx ? 3 : 4)];
        float dimm1 = isx ? (float)(WW - 1) : (float)(HH - 1);
        float an = lo * 0.0625f / dimm1;
        float bn = hi * 0.0625f / dimm1;
        float t  = (float)i / 13.0f;
        float v  = (an + t * (bn - an)) * dimm1;
        float f  = floorf(v);
        int p0   = (int)f;
        int lim  = (int)dimm1;
        int q0   = min(max(p0, 0), lim);
        int q1   = min(max(p0 + 1, 0), lim);
        float w  = v - f;
        unsigned ok = (v >= 0.0f && v <= dimm1) ? 0x3C003C00u : 0u;  // half2 1/0
        if (isx) { sx0[i] = q0; sx1[i] = q1; swx_f[i] = w; svx[i] = ok; }
        else     { sy0[i] = q0; sy1[i] = q1;
                   swy[i] = __float2half2_rn(w); svy[i] = ok; }
    }
    __syncthreads();

    // --- stage 2: per pooled cell structure + dedup case codes ---
    if (tid < 2 * PS) {
        bool isx = tid >= PS;
        int  q   = isx ? tid - PS : tid;
        int  i = 2 * q, j = 2 * q + 1;
        if (!isx) {
            int R0 = sy0[i], R1 = sy1[i], R2 = sy0[j], R3 = sy1[j];
            yCs[q] = (R2 == R0) ? 0 : ((R2 == R1) ? 1 : 2);
            yR0[q] = R0 * (WW * 64); yR1[q] = R1 * (WW * 64);
            yR2[q] = R2 * (WW * 64); yR3[q] = R3 * (WW * 64);
            yVa[q] = svy[i]; yVb[q] = svy[j];
        } else {
            int C0 = sx0[i], C1 = sx1[i], C2 = sx0[j], C3 = sx1[j];
            xCs[q] = (C2 == C0) ? 0 : ((C2 == C1) ? 1 : 2);
            xC0[q] = C0 * 64; xC1[q] = C1 * 64;
            xC2[q] = C2 * 64; xC3[q] = C3 * 64;
            xWa[q] = __float2half2_rn(swx_f[i]);
            xWb[q] = __float2half2_rn(swx_f[j]);
            xVa[q] = svx[i]; xVb[q] = svx[j];
        }
    }
    __syncthreads();

    const int c8 = tid & 63;                      // 8-channel lane index
    const uint4* __restrict__ base = (const uint4*)g_hwc_h + c8;

    auto ldc = [&](int off) -> H8 {
        uint4 g = base[off];
        H8 h;
        h.a = reinterpret_cast<__half2&>(g.x);
        h.b = reinterpret_cast<__half2&>(g.y);
        h.c = reinterpret_cast<__half2&>(g.z);
        h.d = reinterpret_cast<__half2&>(g.w);
        return h;
    };

    const unsigned NEGINF2 = 0xFC00FC00u;         // half2(-inf,-inf)

    int pos = tid >> 6;      // group 0..7
    int py  = pos / 7;       // 0 (or 1 for g=7)
    int px  = pos - py * 7;
    while (pos < 49) {
        const int     c0 = xC0[px], c1 = xC1[px], c2 = xC2[px], c3 = xC3[px];
        const int     xcs = xCs[px];
        const __half2 wxa = xWa[px], wxb = xWb[px];
        const int     r0 = yR0[py], r1 = yR1[py], r2 = yR2[py], r3 = yR3[py];
        const int     ycs = yCs[py];
        const __half2 wya = swy[2 * py], wyb = swy[2 * py + 1];
        // 0/1 half2 masks via HMUL2 (fma pipe)
        const __half2 mya = reinterpret_cast<const __half2&>(yVa[py]);
        const __half2 myb = reinterpret_cast<const __half2&>(yVb[py]);
        const __half2 mxa = reinterpret_cast<const __half2&>(xVa[px]);
        const __half2 mxb = reinterpret_cast<const __half2&>(xVb[px]);
        const __half2 maa = __hmul2(mya, mxa);
        const __half2 mab = __hmul2(mya, mxb);
        const __half2 mba = __hmul2(myb, mxa);
        const __half2 mbb = __hmul2(myb, mxb);

        // horizontal interp for one row, deduping shared columns (uniform branch)
        auto hx_row = [&](int roff, H8& ha, H8& hb) {
            if (xcs == 0) {             // 2 unique cols
                H8 g0 = ldc(roff + c0);
                H8 g1 = ldc(roff + c1);
                ha = lerpH(g0, g1, wxa);
                hb = lerpH(g0, g1, wxb);
            } else if (xcs == 1) {      // 3 unique cols
                H8 g0 = ldc(roff + c0);
                H8 g1 = ldc(roff + c1);
                H8 g3 = ldc(roff + c3);
                ha = lerpH(g0, g1, wxa);
                hb = lerpH(g1, g3, wxb);
            } else {                    // 4 unique cols
                H8 g0 = ldc(roff + c0);
                H8 g1 = ldc(roff + c1);
                H8 g2 = ldc(roff + c2);
                H8 g3 = ldc(roff + c3);
                ha = lerpH(g0, g1, wxa);
                hb = lerpH(g2, g3, wxb);
            }
        };

        H8 m;
        m.a = reinterpret_cast<const __half2&>(NEGINF2);
        m.b = m.a; m.c = m.a; m.d = m.a;

        H8 h0a, h0b, h1a, h1b;
        hx_row(r0, h0a, h0b);
        hx_row(r1, h1a, h1b);
        maxH(m, lerpH(h0a, h1a, wya), maa);
        maxH(m, lerpH(h0b, h1b, wya), mab);

        H8 h2a, h2b, h3a, h3b;
        if (ycs == 0) {                 // reuse both rows
            h2a = h0a; h2b = h0b; h3a = h1a; h3b = h1b;
        } else if (ycs == 1) {          // reuse one row
            h2a = h1a; h2b = h1b;
            hx_row(r3, h3a, h3b);
        } else {
            hx_row(r2, h2a, h2b);
            hx_row(r3, h3a, h3b);
        }
        maxH(m, lerpH(h2a, h3a, wyb), mba);
        maxH(m, lerpH(h2b, h3b, wyb), mbb);

        // stage half2 words: word col = c8 + 64*w holds channels 8c8+2w, +1
        unsigned* st = tile_u + pos * TSTRIDE + c8;
        st[0]   = reinterpret_cast<unsigned&>(m.a);
        st[64]  = reinterpret_cast<unsigned&>(m.b);
        st[128] = reinterpret_cast<unsigned&>(m.c);
        st[192] = reinterpret_cast<unsigned&>(m.d);

        pos += 8;
        px  += 1;
        py  += 1;
        if (px >= 7) { px -= 7; ++py; }
    }
    __syncthreads();

    // --- flush by channel pairs: word (P,pos) -> out[2P*49+pos], [..+49] ---
    // col(P) = (P>>2) + ((P&3)<<6); reads bank-stride 1; both STG streams
    // coalesced.
    float* __restrict__ dst = out + (size_t)r * (CCH * 49);
    int k = tid;
    int P = tid / 49;
    int pos2 = tid - P * 49;
    while (k < 256 * 49) {
        int col = (P >> 2) + ((P & 3) << 6);
        unsigned w = tile_u[pos2 * TSTRIDE + col];
        float2 f = __half22float2(reinterpret_cast<__half2&>(w));
        int o = P * 98 + pos2;
        dst[o]      = f.x;
        dst[o + 49] = f.y;
        k += 512; pos2 += 22; P += 10;    // 512 = 10*49 + 22
        if (pos2 >= 49) { pos2 -= 49; ++P; }
    }
}

// ---------------------------------------------------------------------------
extern "C" void kernel_launch(void* const* d_in, const int* in_sizes, int n_in,
                              void* d_out, int out_size) {
    const float* bottom;
    const float* rois;
    if (n_in >= 2 && in_sizes[0] == 5 * NROI) {
        rois   = (const float*)d_in[0];
        bottom = (const float*)d_in[1];
    } else {
        bottom = (const float*)d_in[0];
        rois   = (const float*)d_in[1];
    }
    float* out = (float*)d_out;

    cudaFuncSetAttribute(roi_kernel,
                         cudaFuncAttributeMaxDynamicSharedMemorySize, SMEM_BYTES);

    dim3 tb(32, 8);
    dim3 tg((HWN + 31) / 32, (CCH + 31) / 32);
    transpose_kernel<<<tg, tb>>>(bottom);
    roi_kernel<<<NROI, 512, SMEM_BYTES>>>(rois, out);
}